// round 1
// baseline (speedup 1.0000x reference)
#include <cuda_runtime.h>
#include <cuda_bf16.h>

// SSIM fused kernel for X,Y: [64,1,320,320] f32, window: [1,1,7,7] f32 (rank-1 Gaussian).
// output: scalar f32 = 1 - mean(ssim_map)

#define IMG_H 320
#define IMG_W 320
#define N_IMG 64
#define TS 32          // output tile 32x32
#define HALO 3
#define IN_TS 38       // TS + 2*HALO
#define IN_STRIDE 41   // padded: conflict-free for 10-wide strided reads
#define HB_STRIDE 33   // padded: conflict-free for strided STS + column LDS

#define C1_CONST 0.0004f                 // (0.01*2)^2
#define C2_CONST 0.0036f                 // (0.03*2)^2
#define COV_NORM_CONST (49.0f / 48.0f)   // NP/(NP-1)

__device__ double g_acc;

__global__ void zero_acc_kernel() { g_acc = 0.0; }

__global__ void finalize_kernel(float* out) {
    double total = (double)N_IMG * IMG_H * IMG_W;
    out[0] = (float)(1.0 - g_acc / total);
}

__global__ __launch_bounds__(256, 4)
void ssim_kernel(const float* __restrict__ X, const float* __restrict__ Y,
                 const float* __restrict__ W) {
    __shared__ float sX[IN_TS * IN_STRIDE];
    __shared__ float sY[IN_TS * IN_STRIDE];
    __shared__ float hbuf[5][IN_TS * HB_STRIDE];
    __shared__ float warp_sums[8];

    const int n  = blockIdx.z;
    const int bx = blockIdx.x * TS;
    const int by = blockIdx.y * TS;
    const int tid = threadIdx.x;

    // Recover separable 1-D weights u_i = g_i / sqrt(S) from the rank-1 window:
    // W[i][j] = g_i g_j / S  ->  W[i][3]/sqrt(W[3][3]) = g_i/sqrt(S).
    float wt[7];
    {
        float wc = sqrtf(W[3 * 7 + 3]);
        #pragma unroll
        for (int i = 0; i < 7; i++) wt[i] = W[i * 7 + 3] / wc;
    }

    const float* Xn = X + (size_t)n * IMG_H * IMG_W;
    const float* Yn = Y + (size_t)n * IMG_H * IMG_W;

    // ---- Load 38x38 halo tiles (zero padding at borders) ----
    for (int i = tid; i < IN_TS * IN_TS; i += 256) {
        int r = i / IN_TS;
        int c = i - r * IN_TS;
        int gy = by + r - HALO;
        int gx = bx + c - HALO;
        bool inb = (gy >= 0) & (gy < IMG_H) & (gx >= 0) & (gx < IMG_W);
        float xv = 0.f, yv = 0.f;
        if (inb) {
            int gidx = gy * IMG_W + gx;
            xv = Xn[gidx];
            yv = Yn[gidx];
        }
        sX[r * IN_STRIDE + c] = xv;
        sY[r * IN_STRIDE + c] = yv;
    }
    __syncthreads();

    // ---- Horizontal pass: 38 rows x 32 output cols, 5 streams ----
    // Tasks: 38 rows * 8 col-groups of 4 = 304. Sliding window: 10 loads -> 4 outputs.
    for (int t = tid; t < IN_TS * 8; t += 256) {
        int r  = t >> 3;
        int c0 = (t & 7) * 4;
        float xv[10], yv[10];
        #pragma unroll
        for (int k = 0; k < 10; k++) {
            xv[k] = sX[r * IN_STRIDE + c0 + k];
            yv[k] = sY[r * IN_STRIDE + c0 + k];
        }
        #pragma unroll
        for (int j = 0; j < 4; j++) {
            float sx = 0.f, sy = 0.f, sxx = 0.f, syy = 0.f, sxy = 0.f;
            #pragma unroll
            for (int k = 0; k < 7; k++) {
                float w = wt[k];
                float x = xv[j + k];
                float y = yv[j + k];
                float wx = w * x;
                float wy = w * y;
                sx += wx;
                sy += wy;
                sxx = fmaf(wx, x, sxx);
                syy = fmaf(wy, y, syy);
                sxy = fmaf(wx, y, sxy);
            }
            int o = r * HB_STRIDE + c0 + j;
            hbuf[0][o] = sx;
            hbuf[1][o] = sy;
            hbuf[2][o] = sxx;
            hbuf[3][o] = syy;
            hbuf[4][o] = sxy;
        }
    }
    __syncthreads();

    // ---- Vertical pass + SSIM formula ----
    // Thread (tx, ty): column tx, output rows ty*4 .. ty*4+3 (sliding 10 -> 4).
    const int tx = tid & 31;
    const int ty = tid >> 5;

    float res[5][4];
    #pragma unroll
    for (int s = 0; s < 5; s++) {
        float v[10];
        #pragma unroll
        for (int k = 0; k < 10; k++)
            v[k] = hbuf[s][(ty * 4 + k) * HB_STRIDE + tx];
        #pragma unroll
        for (int j = 0; j < 4; j++) {
            float sum = 0.f;
            #pragma unroll
            for (int k = 0; k < 7; k++)
                sum = fmaf(wt[k], v[j + k], sum);
            res[s][j] = sum;
        }
    }

    float facc = 0.f;
    #pragma unroll
    for (int j = 0; j < 4; j++) {
        float mux = res[0][j];
        float muy = res[1][j];
        float mux2 = mux * mux;
        float muy2 = muy * muy;
        float muxy = mux * muy;
        float sxx = (res[2][j] - mux2) * COV_NORM_CONST;
        float syy = (res[3][j] - muy2) * COV_NORM_CONST;
        float sxy = (res[4][j] - muxy) * COV_NORM_CONST;
        float num = (2.f * muxy + C1_CONST) * (2.f * sxy + C2_CONST);
        float den = (mux2 + muy2 + C1_CONST) * (sxx + syy + C2_CONST);
        facc += num / den;
    }

    // ---- Block reduction -> one double atomic per block ----
    #pragma unroll
    for (int off = 16; off > 0; off >>= 1)
        facc += __shfl_down_sync(0xffffffffu, facc, off);
    if (tx == 0) warp_sums[ty] = facc;
    __syncthreads();
    if (tid == 0) {
        double bs = 0.0;
        #pragma unroll
        for (int w = 0; w < 8; w++) bs += (double)warp_sums[w];
        atomicAdd(&g_acc, bs);
    }
}

extern "C" void kernel_launch(void* const* d_in, const int* in_sizes, int n_in,
                              void* d_out, int out_size) {
    const float* X = (const float*)d_in[0];
    const float* Y = (const float*)d_in[1];
    const float* W = (const float*)d_in[2];
    float* out = (float*)d_out;

    zero_acc_kernel<<<1, 1>>>();
    dim3 grid(IMG_W / TS, IMG_H / TS, N_IMG);
    ssim_kernel<<<grid, 256>>>(X, Y, W);
    finalize_kernel<<<1, 1>>>(out);
}

// round 2
// speedup vs baseline: 1.0618x; 1.0618x over previous
#include <cuda_runtime.h>
#include <cuda_bf16.h>

// SSIM fused, f32x2-packed. X,Y: [64,1,320,320] f32; window [1,1,7,7] rank-1 Gaussian.
// out: scalar f32 = 1 - mean(ssim_map).
//
// Tile = 64 wide x 32 tall. The two 32-wide halves of the tile are packed into
// f32x2 register pairs (lo = col c, hi = col c+32); all conv FMAs and the SSIM
// formula run on packed fma.rn.f32x2 / mul.rn.f32x2 (2 outputs per instruction).

typedef unsigned long long u64;

#define IMG_H 320
#define IMG_W 320
#define N_IMG 64
#define TILE_W 64
#define TILE_H 32
#define HALO 3
#define IN_R   38            // TILE_H + 6 halo rows
#define IN_PC  38            // pair-columns (pair p = cols (p-3, p+29) rel. tile)
#define IN_ST  42            // pair stride: 336B -> conflict-free LDS.128 phases
#define HB_ST  42            // hbuf row stride (pairs), same property
#define HB_CS  (32 * HB_ST)  // hbuf per-stream stride: [5][32 cols][42 rows]
#define SMEM_U64 (2 * IN_R * IN_ST + 5 * HB_CS)   // 9912 u64 = 79296 B
#define NBLOCKS (5 * 10 * 64)

#define C1_CONST 0.0004f
#define C2_CONST 0.0036f
#define COV_NORM_CONST (49.0f / 48.0f)

__device__ double g_part[NBLOCKS];

__device__ __forceinline__ u64 pack2(float lo, float hi) {
    u64 d; asm("mov.b64 %0, {%1,%2};" : "=l"(d) : "f"(lo), "f"(hi)); return d;
}
__device__ __forceinline__ void unpack2(u64 v, float& lo, float& hi) {
    asm("mov.b64 {%0,%1}, %2;" : "=f"(lo), "=f"(hi) : "l"(v));
}
__device__ __forceinline__ u64 fma2(u64 a, u64 b, u64 c) {
    u64 d; asm("fma.rn.f32x2 %0, %1, %2, %3;" : "=l"(d) : "l"(a), "l"(b), "l"(c)); return d;
}
__device__ __forceinline__ u64 mul2(u64 a, u64 b) {
    u64 d; asm("mul.rn.f32x2 %0, %1, %2;" : "=l"(d) : "l"(a), "l"(b)); return d;
}
__device__ __forceinline__ u64 add2(u64 a, u64 b) {
    u64 d; asm("add.rn.f32x2 %0, %1, %2;" : "=l"(d) : "l"(a), "l"(b)); return d;
}

__global__ __launch_bounds__(256)
void ssim_kernel(const float* __restrict__ X, const float* __restrict__ Y,
                 const float* __restrict__ W) {
    extern __shared__ u64 sm[];
    u64* sX = sm;
    u64* sY = sm + IN_R * IN_ST;
    u64* sH = sm + 2 * IN_R * IN_ST;   // [5][32][42]
    __shared__ float warp_sums[8];

    const int tid = threadIdx.x;
    const int bx = blockIdx.x * TILE_W;
    const int by = blockIdx.y * TILE_H;
    const int n  = blockIdx.z;

    // Recover separable weights from rank-1 window: u_i = W[i][3]/sqrt(W[3][3])
    float wt[7];
    u64 wp[7];
    {
        float wc = sqrtf(W[3 * 7 + 3]);
        #pragma unroll
        for (int i = 0; i < 7; i++) {
            wt[i] = W[i * 7 + 3] / wc;
            wp[i] = pack2(wt[i], wt[i]);
        }
    }

    const float* Xn = X + (size_t)n * IMG_H * IMG_W;
    const float* Yn = Y + (size_t)n * IMG_H * IMG_W;

    // ---- Load 38 rows x 38 pair-columns; pair p = (col p-3, col p+29) ----
    for (int i = tid; i < IN_R * IN_PC; i += 256) {
        int r = i / IN_PC;
        int c = i - r * IN_PC;
        int gy = by + r - HALO;
        int cl = bx + c - HALO;
        int cr = cl + 32;
        float xl = 0.f, xr = 0.f, yl = 0.f, yr = 0.f;
        if ((unsigned)gy < (unsigned)IMG_H) {
            const float* xrow = Xn + gy * IMG_W;
            const float* yrow = Yn + gy * IMG_W;
            if ((unsigned)cl < (unsigned)IMG_W) { xl = xrow[cl]; yl = yrow[cl]; }
            if ((unsigned)cr < (unsigned)IMG_W) { xr = xrow[cr]; yr = yrow[cr]; }
        }
        sX[r * IN_ST + c] = pack2(xl, xr);
        sY[r * IN_ST + c] = pack2(yl, yr);
    }
    __syncthreads();

    // ---- Horizontal pass: 38 rows x 8 col-groups; writes transposed hbuf ----
    for (int tt = tid; tt < IN_R * 8; tt += 256) {
        int cg = tt / IN_R;
        int r  = tt - cg * IN_R;
        int c0 = cg * 4;
        const u64* px = sX + r * IN_ST + c0;
        const u64* py = sY + r * IN_ST + c0;
        u64 xw[10], yw[10];
        #pragma unroll
        for (int k = 0; k < 5; k++) {
            ulonglong2 vx = *(const ulonglong2*)(px + 2 * k);
            ulonglong2 vy = *(const ulonglong2*)(py + 2 * k);
            xw[2 * k] = vx.x; xw[2 * k + 1] = vx.y;
            yw[2 * k] = vy.x; yw[2 * k + 1] = vy.y;
        }
        #pragma unroll
        for (int j = 0; j < 4; j++) {
            u64 sx = 0, sy = 0, sxx = 0, syy = 0, sxy = 0;
            #pragma unroll
            for (int k = 0; k < 7; k++) {
                u64 x = xw[j + k], y = yw[j + k], w = wp[k];
                sx = fma2(x, w, sx);
                sy = fma2(y, w, sy);
                u64 wx = mul2(x, w);
                u64 wy = mul2(y, w);
                sxx = fma2(wx, x, sxx);
                syy = fma2(wy, y, syy);
                sxy = fma2(wx, y, sxy);
            }
            u64* h = sH + (c0 + j) * HB_ST + r;
            h[0 * HB_CS] = sx;
            h[1 * HB_CS] = sy;
            h[2 * HB_CS] = sxx;
            h[3 * HB_CS] = syy;
            h[4 * HB_CS] = sxy;
        }
    }
    __syncthreads();

    // ---- Vertical pass + SSIM (packed halves) ----
    const int c  = tid & 31;
    const int r0 = (tid >> 5) * 4;

    u64 res[5][4];
    #pragma unroll
    for (int s = 0; s < 5; s++) {
        const u64* h = sH + s * HB_CS + c * HB_ST + r0;
        u64 vw[10];
        #pragma unroll
        for (int k = 0; k < 5; k++) {
            ulonglong2 v = *(const ulonglong2*)(h + 2 * k);
            vw[2 * k] = v.x; vw[2 * k + 1] = v.y;
        }
        #pragma unroll
        for (int j = 0; j < 4; j++) {
            u64 acc = 0;
            #pragma unroll
            for (int k = 0; k < 7; k++)
                acc = fma2(vw[j + k], wp[k], acc);
            res[s][j] = acc;
        }
    }

    const u64 C1p  = pack2(C1_CONST, C1_CONST);
    const u64 C2p  = pack2(C2_CONST, C2_CONST);
    const u64 covp = pack2(COV_NORM_CONST, COV_NORM_CONST);
    const u64 negp = pack2(-1.f, -1.f);
    const u64 twop = pack2(2.f, 2.f);

    float facc = 0.f;
    #pragma unroll
    for (int j = 0; j < 4; j++) {
        u64 mux = res[0][j], muy = res[1][j];
        u64 mux2 = mul2(mux, mux);
        u64 muy2 = mul2(muy, muy);
        u64 muxy = mul2(mux, muy);
        u64 sxx = mul2(fma2(mux2, negp, res[2][j]), covp);
        u64 syy = mul2(fma2(muy2, negp, res[3][j]), covp);
        u64 sxy = mul2(fma2(muxy, negp, res[4][j]), covp);
        u64 num = mul2(fma2(twop, muxy, C1p), fma2(twop, sxy, C2p));
        u64 den = mul2(add2(add2(mux2, muy2), C1p), add2(add2(sxx, syy), C2p));
        float nl, nh, dl, dh;
        unpack2(num, nl, nh);
        unpack2(den, dl, dh);
        facc += __fdividef(nl, dl) + __fdividef(nh, dh);
    }

    // ---- Block reduction -> per-block partial (no atomics, no zeroing) ----
    #pragma unroll
    for (int off = 16; off > 0; off >>= 1)
        facc += __shfl_down_sync(0xffffffffu, facc, off);
    if ((tid & 31) == 0) warp_sums[tid >> 5] = facc;
    __syncthreads();
    if (tid == 0) {
        float bs = 0.f;
        #pragma unroll
        for (int w = 0; w < 8; w++) bs += warp_sums[w];
        int bid = blockIdx.x + 5 * (blockIdx.y + 10 * blockIdx.z);
        g_part[bid] = (double)bs;
    }
}

__global__ void finalize_kernel(float* __restrict__ out) {
    __shared__ double ws[8];
    const int tid = threadIdx.x;
    double s = 0.0;
    for (int i = tid; i < NBLOCKS; i += 256) s += g_part[i];
    #pragma unroll
    for (int off = 16; off > 0; off >>= 1)
        s += __shfl_down_sync(0xffffffffu, s, off);
    if ((tid & 31) == 0) ws[tid >> 5] = s;
    __syncthreads();
    if (tid == 0) {
        double t = 0.0;
        #pragma unroll
        for (int w = 0; w < 8; w++) t += ws[w];
        double total = (double)N_IMG * IMG_H * IMG_W;
        out[0] = (float)(1.0 - t / total);
    }
}

extern "C" void kernel_launch(void* const* d_in, const int* in_sizes, int n_in,
                              void* d_out, int out_size) {
    const float* X = (const float*)d_in[0];
    const float* Y = (const float*)d_in[1];
    const float* W = (const float*)d_in[2];
    float* out = (float*)d_out;

    size_t smem_bytes = (size_t)SMEM_U64 * sizeof(u64);
    cudaFuncSetAttribute(ssim_kernel, cudaFuncAttributeMaxDynamicSharedMemorySize,
                         (int)smem_bytes);

    dim3 grid(IMG_W / TILE_W, IMG_H / TILE_H, N_IMG);
    ssim_kernel<<<grid, 256, smem_bytes>>>(X, Y, W);
    finalize_kernel<<<1, 256>>>(out);
}

// round 3
// speedup vs baseline: 1.1360x; 1.0699x over previous
#include <cuda_runtime.h>
#include <cuda_bf16.h>

// SSIM fused single-kernel, f32x2-packed. X,Y: [64,1,320,320] f32; window 7x7 rank-1.
// out: scalar f32 = 1 - mean(ssim_map).
//
// Tile 64x32; the two 32-wide halves packed into f32x2 (lo = col c, hi = col c+32).
// Phases: gmem->smem halo load; horizontal separable conv (5 streams) -> smem
// (column-major hbuf); vertical conv + SSIM formula in registers; block partial
// -> float g_part[bid]; last block (ticket) reduces in double and writes out.

typedef unsigned long long u64;

#define IMG_H 320
#define IMG_W 320
#define N_IMG 64
#define TILE_W 64
#define TILE_H 32
#define HALO 3
#define IN_R   38            // rows incl. halo
#define IN_PC  38            // pair-columns
#define IN_ST  38            // sX/sY row stride in u64 (bank-checked)
#define HB_COLST 202         // hbuf per-column stride in u64 (bank-checked: 20c mod 32)
#define HB_SST   40          // stream offset within a column
#define SMEM_U64 (2 * IN_R * IN_ST + 32 * HB_COLST)   // 9352 u64 = 74816 B
#define NBLOCKS (5 * 10 * 64)

#define C1_CONST 0.0004f
#define C2_CONST 0.0036f
#define COV_NORM_CONST (49.0f / 48.0f)

__device__ float g_part[NBLOCKS];
__device__ unsigned g_ticket;   // zero-init; atomicInc wraps back to 0 -> replay-safe

__device__ __forceinline__ u64 pack2(float lo, float hi) {
    u64 d; asm("mov.b64 %0, {%1,%2};" : "=l"(d) : "f"(lo), "f"(hi)); return d;
}
__device__ __forceinline__ void unpack2(u64 v, float& lo, float& hi) {
    asm("mov.b64 {%0,%1}, %2;" : "=f"(lo), "=f"(hi) : "l"(v));
}
__device__ __forceinline__ u64 fma2(u64 a, u64 b, u64 c) {
    u64 d; asm("fma.rn.f32x2 %0, %1, %2, %3;" : "=l"(d) : "l"(a), "l"(b), "l"(c)); return d;
}
__device__ __forceinline__ u64 mul2(u64 a, u64 b) {
    u64 d; asm("mul.rn.f32x2 %0, %1, %2;" : "=l"(d) : "l"(a), "l"(b)); return d;
}
__device__ __forceinline__ u64 add2(u64 a, u64 b) {
    u64 d; asm("add.rn.f32x2 %0, %1, %2;" : "=l"(d) : "l"(a), "l"(b)); return d;
}

__global__ __launch_bounds__(256, 3)
void ssim_kernel(const float* __restrict__ X, const float* __restrict__ Y,
                 const float* __restrict__ W, float* __restrict__ out) {
    extern __shared__ u64 sm[];
    u64* sX = sm;
    u64* sY = sm + IN_R * IN_ST;
    u64* sH = sm + 2 * IN_R * IN_ST;   // [32 cols][5 streams x 40 rows]
    __shared__ float warp_sums[8];
    __shared__ int is_last;

    const int tid = threadIdx.x;
    const int bx = blockIdx.x * TILE_W;
    const int by = blockIdx.y * TILE_H;
    const int n  = blockIdx.z;

    // Separable weights from rank-1 window: u_i = W[i][3]/sqrt(W[3][3])
    u64 wp[7];
    {
        float wc = sqrtf(W[3 * 7 + 3]);
        #pragma unroll
        for (int i = 0; i < 7; i++) {
            float w = W[i * 7 + 3] / wc;
            wp[i] = pack2(w, w);
        }
    }

    const float* Xn = X + (size_t)n * IMG_H * IMG_W;
    const float* Yn = Y + (size_t)n * IMG_H * IMG_W;

    // ---- Load 38 rows x 38 pair-cols; pair p = (col p-3, col p+29) ----
    #pragma unroll
    for (int ii = 0; ii < 6; ii++) {
        int i = tid + ii * 256;
        if (i < IN_R * IN_PC) {
            int r = i / IN_PC;
            int c = i - r * IN_PC;
            int gy = by + r - HALO;
            int cl = bx + c - HALO;
            int cr = cl + 32;
            float xl = 0.f, xr = 0.f, yl = 0.f, yr = 0.f;
            if ((unsigned)gy < (unsigned)IMG_H) {
                const float* xrow = Xn + gy * IMG_W;
                const float* yrow = Yn + gy * IMG_W;
                if ((unsigned)cl < (unsigned)IMG_W) { xl = xrow[cl]; yl = yrow[cl]; }
                if ((unsigned)cr < (unsigned)IMG_W) { xr = xrow[cr]; yr = yrow[cr]; }
            }
            sX[r * IN_ST + c] = pack2(xl, xr);
            sY[r * IN_ST + c] = pack2(yl, yr);
        }
    }
    __syncthreads();

    // ---- Horizontal pass: 38 rows x 8 groups of 4 pair-cols ----
    // Main 256 tasks: r = tid&31, cg = tid>>5. Tail 48: r = 32 + (tid>>3), cg = tid&7.
    #pragma unroll
    for (int part = 0; part < 2; part++) {
        int r, cg;
        bool active;
        if (part == 0) { r = tid & 31; cg = tid >> 5; active = true; }
        else           { r = 32 + (tid >> 3); cg = tid & 7; active = (tid < 48); }
        if (active) {
            int c0 = cg * 4;
            const u64* px = sX + r * IN_ST + c0;
            const u64* py = sY + r * IN_ST + c0;
            u64 xw[10], yw[10];
            #pragma unroll
            for (int k = 0; k < 5; k++) {
                ulonglong2 vx = *(const ulonglong2*)(px + 2 * k);
                ulonglong2 vy = *(const ulonglong2*)(py + 2 * k);
                xw[2 * k] = vx.x; xw[2 * k + 1] = vx.y;
                yw[2 * k] = vy.x; yw[2 * k + 1] = vy.y;
            }
            #pragma unroll
            for (int j = 0; j < 4; j++) {
                u64 sx = 0, sy = 0, sxx = 0, syy = 0, sxy = 0;
                #pragma unroll
                for (int k = 0; k < 7; k++) {
                    u64 x = xw[j + k], y = yw[j + k], w = wp[k];
                    sx = fma2(x, w, sx);
                    sy = fma2(y, w, sy);
                    u64 wx = mul2(x, w);
                    u64 wy = mul2(y, w);
                    sxx = fma2(wx, x, sxx);
                    syy = fma2(wy, y, syy);
                    sxy = fma2(wx, y, sxy);
                }
                u64* h = sH + (c0 + j) * HB_COLST + r;
                h[0 * HB_SST] = sx;
                h[1 * HB_SST] = sy;
                h[2 * HB_SST] = sxx;
                h[3 * HB_SST] = syy;
                h[4 * HB_SST] = sxy;
            }
        }
    }
    __syncthreads();

    // ---- Vertical pass + SSIM (packed halves), low live-state ----
    const int c  = tid & 31;
    const int r0 = (tid >> 5) * 4;
    const u64* hcol = sH + c * HB_COLST + r0;

    u64 muxv[4], muyv[4], muxy[4], P[4], S23[4], r4v[4];

    // stream 0: mux
    {
        u64 vw[10];
        #pragma unroll
        for (int k = 0; k < 5; k++) {
            ulonglong2 v = *(const ulonglong2*)(hcol + 0 * HB_SST + 2 * k);
            vw[2 * k] = v.x; vw[2 * k + 1] = v.y;
        }
        #pragma unroll
        for (int j = 0; j < 4; j++) {
            u64 acc = 0;
            #pragma unroll
            for (int k = 0; k < 7; k++) acc = fma2(vw[j + k], wp[k], acc);
            muxv[j] = acc;
        }
    }
    // stream 1: muy -> fold into muxy, P
    {
        u64 vw[10];
        #pragma unroll
        for (int k = 0; k < 5; k++) {
            ulonglong2 v = *(const ulonglong2*)(hcol + 1 * HB_SST + 2 * k);
            vw[2 * k] = v.x; vw[2 * k + 1] = v.y;
        }
        #pragma unroll
        for (int j = 0; j < 4; j++) {
            u64 acc = 0;
            #pragma unroll
            for (int k = 0; k < 7; k++) acc = fma2(vw[j + k], wp[k], acc);
            muyv[j] = acc;
        }
        #pragma unroll
        for (int j = 0; j < 4; j++) {
            muxy[j] = mul2(muxv[j], muyv[j]);
            P[j] = fma2(muxv[j], muxv[j], mul2(muyv[j], muyv[j]));  // mux2 + muy2
        }
    }
    // streams 2,3: S23 = conv(x^2) + conv(y^2)
    #pragma unroll
    for (int s = 2; s <= 3; s++) {
        u64 vw[10];
        #pragma unroll
        for (int k = 0; k < 5; k++) {
            ulonglong2 v = *(const ulonglong2*)(hcol + s * HB_SST + 2 * k);
            vw[2 * k] = v.x; vw[2 * k + 1] = v.y;
        }
        #pragma unroll
        for (int j = 0; j < 4; j++) {
            u64 acc = (s == 2) ? (u64)0 : S23[j];
            #pragma unroll
            for (int k = 0; k < 7; k++) acc = fma2(vw[j + k], wp[k], acc);
            S23[j] = acc;
        }
    }
    // stream 4: conv(xy)
    {
        u64 vw[10];
        #pragma unroll
        for (int k = 0; k < 5; k++) {
            ulonglong2 v = *(const ulonglong2*)(hcol + 4 * HB_SST + 2 * k);
            vw[2 * k] = v.x; vw[2 * k + 1] = v.y;
        }
        #pragma unroll
        for (int j = 0; j < 4; j++) {
            u64 acc = 0;
            #pragma unroll
            for (int k = 0; k < 7; k++) acc = fma2(vw[j + k], wp[k], acc);
            r4v[j] = acc;
        }
    }

    const u64 C1p  = pack2(C1_CONST, C1_CONST);
    const u64 C2p  = pack2(C2_CONST, C2_CONST);
    const u64 covp = pack2(COV_NORM_CONST, COV_NORM_CONST);
    const u64 negp = pack2(-1.f, -1.f);
    const u64 twop = pack2(2.f, 2.f);

    float facc = 0.f;
    #pragma unroll
    for (int j = 0; j < 4; j++) {
        // sxy = (r4 - muxy)*cov ; sxx+syy = (S23 - P)*cov
        u64 sxy  = mul2(fma2(muxy[j], negp, r4v[j]), covp);
        u64 ssum = mul2(fma2(P[j],    negp, S23[j]), covp);
        u64 num = mul2(fma2(twop, muxy[j], C1p), fma2(twop, sxy, C2p));
        u64 den = mul2(add2(P[j], C1p), add2(ssum, C2p));
        float nl, nh, dl, dh;
        unpack2(num, nl, nh);
        unpack2(den, dl, dh);
        facc += __fdividef(nl, dl) + __fdividef(nh, dh);
    }

    // ---- Block reduction -> per-block partial ----
    #pragma unroll
    for (int off = 16; off > 0; off >>= 1)
        facc += __shfl_down_sync(0xffffffffu, facc, off);
    if ((tid & 31) == 0) warp_sums[tid >> 5] = facc;
    __syncthreads();
    if (tid == 0) {
        float bs = 0.f;
        #pragma unroll
        for (int w = 0; w < 8; w++) bs += warp_sums[w];
        int bid = blockIdx.x + 5 * (blockIdx.y + 10 * blockIdx.z);
        g_part[bid] = bs;
        __threadfence();
        unsigned ticket = atomicInc(&g_ticket, NBLOCKS - 1);
        is_last = (ticket == NBLOCKS - 1);
    }
    __syncthreads();

    // ---- Last block: final reduction (double, fixed order -> deterministic) ----
    if (is_last) {
        __shared__ double dsums[8];
        double s = 0.0;
        for (int i = tid; i < NBLOCKS; i += 256) s += (double)__ldcg(&g_part[i]);
        #pragma unroll
        for (int off = 16; off > 0; off >>= 1)
            s += __shfl_down_sync(0xffffffffu, s, off);
        if ((tid & 31) == 0) dsums[tid >> 5] = s;
        __syncthreads();
        if (tid == 0) {
            double t = 0.0;
            #pragma unroll
            for (int w = 0; w < 8; w++) t += dsums[w];
            double total = (double)N_IMG * IMG_H * IMG_W;
            out[0] = (float)(1.0 - t / total);
        }
    }
}

extern "C" void kernel_launch(void* const* d_in, const int* in_sizes, int n_in,
                              void* d_out, int out_size) {
    const float* X = (const float*)d_in[0];
    const float* Y = (const float*)d_in[1];
    const float* W = (const float*)d_in[2];
    float* out = (float*)d_out;

    size_t smem_bytes = (size_t)SMEM_U64 * sizeof(u64);
    cudaFuncSetAttribute(ssim_kernel, cudaFuncAttributeMaxDynamicSharedMemorySize,
                         (int)smem_bytes);

    dim3 grid(IMG_W / TILE_W, IMG_H / TILE_H, N_IMG);
    ssim_kernel<<<grid, 256, smem_bytes>>>(X, Y, W, out);
}